// round 13
// baseline (speedup 1.0000x reference)
#include <cuda_runtime.h>
#include <cuda_bf16.h>
#include <cstdint>

// Problem constants (fixed by setup_inputs)
#define RES        64
#define N_PHAL     20
#define BATCH      256
#define N_TILES    (BATCH * N_PHAL)      // 5120 (b,p) tiles
#define TILE_FLT   (RES * RES * 5)       // 20480 floats = 80 KB per tile
#define CHUNK_PX   512                   // pixels per chunk
#define CHUNK_FLT  (CHUNK_PX * 5)        // 2560 floats = 10 KB
#define CHUNK_B    (CHUNK_FLT * 4)       // 10240 bytes
#define CPT        8                     // chunks per tile
#define STAGES     3
#define GRID       1036                  // 148 SMs x 7 persistent blocks
#define OUT_ROWS   (N_PHAL + 1)          // 21

__device__ __forceinline__ unsigned smem_u32(const void* p) {
    return (unsigned)__cvta_generic_to_shared(p);
}

__device__ __forceinline__ void mbar_init(unsigned mbar, unsigned count) {
    asm volatile("mbarrier.init.shared.b64 [%0], %1;" :: "r"(mbar), "r"(count) : "memory");
}
__device__ __forceinline__ void mbar_expect_tx(unsigned mbar, unsigned bytes) {
    asm volatile("mbarrier.arrive.expect_tx.shared.b64 _, [%0], %1;"
                 :: "r"(mbar), "r"(bytes) : "memory");
}
__device__ __forceinline__ void mbar_wait(unsigned mbar, unsigned parity) {
    asm volatile(
        "{\n\t"
        ".reg .pred P;\n\t"
        "W%=:\n\t"
        "mbarrier.try_wait.parity.acquire.cta.shared::cta.b64 P, [%0], %1, 0x989680;\n\t"
        "@P bra D%=;\n\t"
        "bra W%=;\n\t"
        "D%=:\n\t"
        "}"
        :: "r"(mbar), "r"(parity) : "memory");
}
__device__ __forceinline__ void bulk_cp(unsigned dst, const void* src, unsigned bytes,
                                        unsigned mbar) {
    asm volatile(
        "cp.async.bulk.shared::cta.global.mbarrier::complete_tx::bytes [%0], [%1], %2, [%3];"
        :: "r"(dst), "l"(src), "r"(bytes), "r"(mbar) : "memory");
}
__device__ __forceinline__ void fence_async_shared() {
    asm volatile("fence.proxy.async.shared::cta;" ::: "memory");
}

// ---------------------------------------------------------------------------
// Zero the 256 x 21 x 2 output (poisoned to 0xAA before timing).
// ---------------------------------------------------------------------------
__global__ void zero_out_kernel(float* __restrict__ out)
{
    const int i = blockIdx.x * blockDim.x + threadIdx.x;
    if (i < BATCH * OUT_ROWS * 2) out[i] = 0.f;
}

// ---------------------------------------------------------------------------
// Persistent fused reduction + keypoint scatter.
// Block k owns tiles k, k+GRID, k+2*GRID, ... (4-5 tiles each, 80 KB
// contiguous per tile). Flat chunk stream (8 chunks/tile, 10 KB each) runs
// through a 3-stage TMA-bulk + mbarrier pipeline; one elected thread moves
// each chunk with a single cp.async.bulk. 256 threads consume 2 pixels each
// via stride-5 LDS (conflict-free, gcd(5,32)==1). At tile end: block-reduce
// 5 accumulators and atomically scatter into the output keypoint rows.
//
// Scatter map for phalanx p = 4i + j (verified R4/R7, rel_err 8.9e-8):
//   vs[p] -> row 4i+4-j, weight (j==3 ? 1 : 0.5)
//   vf[p] -> j>=1: row 4i+5-j, weight 0.5 ; j==0: row 0, weight 0.2
// ---------------------------------------------------------------------------
__global__ __launch_bounds__(256) void reduce_kernel(const float* __restrict__ x,
                                                     float* __restrict__ out)
{
    __shared__ __align__(128) float sbuf[STAGES][CHUNK_FLT];  // 3 x 10 KB
    __shared__ __align__(8) unsigned long long mbar_s[STAGES];
    __shared__ float red[8][5];

    const int t    = threadIdx.x;
    const int lane = t & 31;
    const int wid  = t >> 5;
    const int blk  = blockIdx.x;

    const int ntiles = (N_TILES - blk + GRID - 1) / GRID;   // 4 or 5
    const int NC     = ntiles * CPT;

    const unsigned mb0 = smem_u32(&mbar_s[0]);

    if (t == 0) {
        #pragma unroll
        for (int s = 0; s < STAGES; ++s) mbar_init(mb0 + 8u * s, 1u);
        fence_async_shared();
    }
    __syncthreads();

    auto src_of = [&](int cc) -> const float* {
        const int tile = blk + (cc >> 3) * GRID;
        return x + (size_t)tile * TILE_FLT + (size_t)(cc & 7) * CHUNK_FLT;
    };
    auto issue = [&](int cc) {
        const unsigned mb = mb0 + 8u * (unsigned)(cc % STAGES);
        mbar_expect_tx(mb, CHUNK_B);
        bulk_cp(smem_u32(sbuf[cc % STAGES]), src_of(cc), CHUNK_B, mb);
    };

    if (t == 0) { issue(0); issue(1); issue(2); }

    const float ljf = (float)(t & 63);
    const int   lib = t >> 6;                     // row base of pixel t

    float den = 0.f, vf0 = 0.f, vf1 = 0.f, vs0 = 0.f, vs1 = 0.f;

    #pragma unroll 1
    for (int cc = 0; cc < NC; ++cc) {
        const int      stg = cc % STAGES;
        const unsigned par = (unsigned)((cc / STAGES) & 1);
        mbar_wait(mb0 + 8u * stg, par);

        const float* __restrict__ sp = sbuf[stg];
        const float libase = (float)(((cc & 7) << 3) + lib);

        #pragma unroll
        for (int k = 0; k < 2; ++k) {
            const float* __restrict__ q = sp + (t + (k << 8)) * 5;
            const float f0 = q[0];
            const float f1 = q[1];
            const float m  = q[2];
            const float d0 = q[3];
            const float d1 = q[4];

            const float li = libase + (float)(k << 2);
            const float a  = fabsf(m);
            const float t0 = f1 * m;
            const float t1 = -f0 * m;

            den += a;
            vf0 += a * fmaf( t0, d0, li);
            vf1 += a * fmaf( t1, d0, ljf);
            vs0 += a * fmaf(-t0, d1, li);
            vs1 += a * fmaf(-t1, d1, ljf);
        }

        const bool tile_end = ((cc & 7) == 7);
        if (tile_end) {
            float v0 = den, v1 = vf0, v2 = vf1, v3 = vs0, v4 = vs1;
            #pragma unroll
            for (int o = 16; o; o >>= 1) {
                v0 += __shfl_xor_sync(0xffffffffu, v0, o);
                v1 += __shfl_xor_sync(0xffffffffu, v1, o);
                v2 += __shfl_xor_sync(0xffffffffu, v2, o);
                v3 += __shfl_xor_sync(0xffffffffu, v3, o);
                v4 += __shfl_xor_sync(0xffffffffu, v4, o);
            }
            if (lane == 0) {
                red[wid][0] = v0; red[wid][1] = v1; red[wid][2] = v2;
                red[wid][3] = v3; red[wid][4] = v4;
            }
            den = vf0 = vf1 = vs0 = vs1 = 0.f;
        }

        __syncthreads();   // stage consumed by all; red[] (if any) published

        if (t == 0) {
            if (cc + STAGES < NC) {
                fence_async_shared();
                issue(cc + STAGES);
            }
            if (tile_end) {
                float r0 = 0.f, r1 = 0.f, r2 = 0.f, r3 = 0.f, r4 = 0.f;
                #pragma unroll
                for (int w = 0; w < 8; ++w) {
                    r0 += red[w][0]; r1 += red[w][1]; r2 += red[w][2];
                    r3 += red[w][3]; r4 += red[w][4];
                }
                const float inv  = (r0 == 0.f) ? 1.f : 1.f / r0;
                const float mvf0 = r1 * inv, mvf1 = r2 * inv;
                const float mvs0 = r3 * inv, mvs1 = r4 * inv;

                const int tile = blk + (cc >> 3) * GRID;
                const int b = tile / N_PHAL;
                const int p = tile % N_PHAL;
                const int i = p >> 2, j = p & 3;
                float* __restrict__ ob = out + b * OUT_ROWS * 2;

                const int   r_s = 4 * i + 4 - j;
                const float w_s = (j == 3) ? 1.f : 0.5f;
                atomicAdd(ob + r_s * 2 + 0, mvs0 * w_s);
                atomicAdd(ob + r_s * 2 + 1, mvs1 * w_s);

                if (j) {
                    const int r_f = 4 * i + 5 - j;
                    atomicAdd(ob + r_f * 2 + 0, 0.5f * mvf0);
                    atomicAdd(ob + r_f * 2 + 1, 0.5f * mvf1);
                } else {
                    atomicAdd(ob + 0, 0.2f * mvf0);
                    atomicAdd(ob + 1, 0.2f * mvf1);
                }
            }
        }
    }
}

extern "C" void kernel_launch(void* const* d_in, const int* in_sizes, int n_in,
                              void* d_out, int out_size)
{
    const float* x = (const float*)d_in[0];
    float* out = (float*)d_out;

    zero_out_kernel<<<(BATCH * OUT_ROWS * 2 + 255) / 256, 256>>>(out);
    reduce_kernel<<<GRID, 256>>>(x, out);
}